// round 1
// baseline (speedup 1.0000x reference)
#include <cuda_runtime.h>
#include <cstddef>

#define Bx 16
#define Lx 4096
#define Dx 1024

// ---- scratch (no allocation allowed; __device__ globals) ----
__device__ float g_df[Bx * Dx];          // dec_feature
__device__ float g_score[Bx * Lx];       // pre-softmax scores
__device__ float g_partial[Bx * 32 * Dx]; // context partials (32 l-splits)

// offsets in d_out (float32): attn, context, new_coverage concatenated
#define ATTN_OFF 0
#define CTX_OFF  (Bx * Lx)
#define COV_OFF  (Bx * Lx + Bx * Dx)

// ============================================================
// Kernel 1: dec_feature[b,d] = sum_k dec_hidden[b,k]*W_feat[d,k] + b_feat[d]
// grid = Dx blocks, 256 threads. Each thread owns one float4 of row d.
// ============================================================
__global__ void k_decfeat(const float* __restrict__ dh,
                          const float* __restrict__ W,
                          const float* __restrict__ bias) {
    int d = blockIdx.x;
    int t = threadIdx.x;               // 0..255
    float4 w4 = ((const float4*)(W + (size_t)d * Dx))[t];

    float acc[Bx];
#pragma unroll
    for (int b = 0; b < Bx; b++) {
        float4 h4 = ((const float4*)(dh + (size_t)b * Dx))[t];
        acc[b] = w4.x * h4.x + w4.y * h4.y + w4.z * h4.z + w4.w * h4.w;
    }
#pragma unroll
    for (int b = 0; b < Bx; b++) {
#pragma unroll
        for (int off = 16; off; off >>= 1)
            acc[b] += __shfl_down_sync(0xffffffffu, acc[b], off);
    }
    __shared__ float s[8][Bx];
    int warp = t >> 5, lane = t & 31;
    if (lane == 0) {
#pragma unroll
        for (int b = 0; b < Bx; b++) s[warp][b] = acc[b];
    }
    __syncthreads();
    if (t < Bx) {
        float v = 0.f;
#pragma unroll
        for (int w = 0; w < 8; w++) v += s[w][t];
        g_df[t * Dx + d] = v + bias[d];
    }
}

// ============================================================
// Kernel 2: score[b,l] = sum_d tanh(ef + df + cov*w_cov) * w_score
// grid = (Lx/8, Bx), 256 threads = 8 warps, one warp per l-row.
// Streams enc_feature (256 MB) — HBM bound.
// ============================================================
__global__ void k_score(const float* __restrict__ ef,
                        const float* __restrict__ cov,
                        const float* __restrict__ wscore,
                        const float* __restrict__ wcov) {
    int b  = blockIdx.y;
    int l0 = blockIdx.x * 8;
    int t  = threadIdx.x;

    __shared__ float4 s_df[Dx / 4], s_ws[Dx / 4], s_wc[Dx / 4];
    s_df[t] = ((const float4*)(g_df + (size_t)b * Dx))[t];
    s_ws[t] = ((const float4*)wscore)[t];
    s_wc[t] = ((const float4*)wcov)[t];
    __syncthreads();

    int warp = t >> 5, lane = t & 31;
    int l = l0 + warp;
    float c = cov[b * Lx + l];
    const float4* row = (const float4*)(ef + ((size_t)b * Lx + l) * Dx);

    float sum = 0.f;
#pragma unroll
    for (int j = 0; j < 8; j++) {
        int idx = lane + j * 32;
        float4 e  = row[idx];
        float4 dv = s_df[idx];
        float4 wc = s_wc[idx];
        float4 ws = s_ws[idx];
        sum += tanhf(fmaf(c, wc.x, e.x + dv.x)) * ws.x
             + tanhf(fmaf(c, wc.y, e.y + dv.y)) * ws.y
             + tanhf(fmaf(c, wc.z, e.z + dv.z)) * ws.z
             + tanhf(fmaf(c, wc.w, e.w + dv.w)) * ws.w;
    }
#pragma unroll
    for (int off = 16; off; off >>= 1)
        sum += __shfl_down_sync(0xffffffffu, sum, off);
    if (lane == 0) g_score[b * Lx + l] = sum;
}

// ============================================================
// Kernel 3: masked softmax + renormalize, write attn & new_coverage.
// softmax -> *mask -> /sum collapses to e*m / sum(e*m).
// grid = Bx blocks, 1024 threads, 4 elems/thread.
// ============================================================
__global__ void k_softmax(const float* __restrict__ mask,
                          const float* __restrict__ cov,
                          float* __restrict__ out) {
    int b = blockIdx.x;
    int t = threadIdx.x;
    __shared__ float red[32];
    __shared__ float bcast;

    float s[4], em[4];
#pragma unroll
    for (int i = 0; i < 4; i++) s[i] = g_score[b * Lx + t + i * 1024];

    // ---- block max ----
    float mx = fmaxf(fmaxf(s[0], s[1]), fmaxf(s[2], s[3]));
#pragma unroll
    for (int off = 16; off; off >>= 1)
        mx = fmaxf(mx, __shfl_xor_sync(0xffffffffu, mx, off));
    if ((t & 31) == 0) red[t >> 5] = mx;
    __syncthreads();
    if (t < 32) {
        float v = red[t];
#pragma unroll
        for (int off = 16; off; off >>= 1)
            v = fmaxf(v, __shfl_xor_sync(0xffffffffu, v, off));
        if (t == 0) bcast = v;
    }
    __syncthreads();
    mx = bcast;

    // ---- e * mask, block sum ----
    float lsum = 0.f;
#pragma unroll
    for (int i = 0; i < 4; i++) {
        em[i] = expf(s[i] - mx) * mask[b * Lx + t + i * 1024];
        lsum += em[i];
    }
#pragma unroll
    for (int off = 16; off; off >>= 1)
        lsum += __shfl_xor_sync(0xffffffffu, lsum, off);
    __syncthreads();            // protect red[] reuse
    if ((t & 31) == 0) red[t >> 5] = lsum;
    __syncthreads();
    if (t < 32) {
        float v = red[t];
#pragma unroll
        for (int off = 16; off; off >>= 1)
            v += __shfl_xor_sync(0xffffffffu, v, off);
        if (t == 0) bcast = v;
    }
    __syncthreads();
    float inv = 1.f / bcast;

#pragma unroll
    for (int i = 0; i < 4; i++) {
        int idx = b * Lx + t + i * 1024;
        float a = em[i] * inv;
        out[ATTN_OFF + idx] = a;
        out[COV_OFF  + idx] = a + cov[idx];
    }
}

// ============================================================
// Kernel 4: context partials. grid = (32 l-splits, Bx), 256 threads.
// Thread owns one float4 of d. Streams enc_output (256 MB) — HBM bound.
// ============================================================
__global__ void k_context(const float* __restrict__ eo,
                          const float* __restrict__ attn) {
    int b  = blockIdx.y;
    int sp = blockIdx.x;     // 0..31
    int t  = threadIdx.x;    // 0..255
    int l0 = sp * 128;

    __shared__ float sa[128];
    if (t < 128) sa[t] = attn[b * Lx + l0 + t];
    __syncthreads();

    const float4* base = (const float4*)eo + ((size_t)b * Lx + l0) * (Dx / 4) + t;
    float4 acc = make_float4(0.f, 0.f, 0.f, 0.f);
#pragma unroll 4
    for (int i = 0; i < 128; i++) {
        float a = sa[i];
        float4 v = base[(size_t)i * (Dx / 4)];
        acc.x = fmaf(a, v.x, acc.x);
        acc.y = fmaf(a, v.y, acc.y);
        acc.z = fmaf(a, v.z, acc.z);
        acc.w = fmaf(a, v.w, acc.w);
    }
    ((float4*)(g_partial + ((size_t)(b * 32 + sp)) * Dx))[t] = acc;
}

// ============================================================
// Kernel 5: deterministic partial reduce -> context. 16384 outputs.
// ============================================================
__global__ void k_reduce(float* __restrict__ out) {
    int idx = blockIdx.x * 256 + threadIdx.x;   // 0..16383
    int b = idx >> 10, d = idx & 1023;
    float v = 0.f;
#pragma unroll
    for (int s = 0; s < 32; s++)
        v += g_partial[((size_t)(b * 32 + s) << 10) + d];
    out[CTX_OFF + idx] = v;
}

// ============================================================
extern "C" void kernel_launch(void* const* d_in, const int* in_sizes, int n_in,
                              void* d_out, int out_size) {
    const float* dec_hidden  = (const float*)d_in[0];
    const float* enc_output  = (const float*)d_in[1];
    const float* enc_feature = (const float*)d_in[2];
    const float* enc_mask    = (const float*)d_in[3];
    // d_in[4] = sec_attn : dead code in reference
    const float* coverage    = (const float*)d_in[5];
    const float* W_feat      = (const float*)d_in[6];
    const float* b_feat      = (const float*)d_in[7];
    const float* w_score     = (const float*)d_in[8];
    const float* w_cov       = (const float*)d_in[9];
    float* out = (float*)d_out;

    k_decfeat<<<Dx, 256>>>(dec_hidden, W_feat, b_feat);
    k_score  <<<dim3(Lx / 8, Bx), 256>>>(enc_feature, coverage, w_score, w_cov);
    k_softmax<<<Bx, 1024>>>(enc_mask, coverage, out);
    k_context<<<dim3(32, Bx), 256>>>(enc_output, out + ATTN_OFF);
    k_reduce <<<(Bx * Dx) / 256, 256>>>(out);
}

// round 2
// speedup vs baseline: 1.0469x; 1.0469x over previous
#include <cuda_runtime.h>
#include <cstddef>

#define Bx 16
#define Lx 4096
#define Dx 1024
#define NSPLIT 64
#define ROWS_PER_SPLIT (Lx / NSPLIT)   // 64

// ---- scratch (no allocation allowed; __device__ globals) ----
__device__ float g_df[Bx * Dx];               // dec_feature
__device__ float g_score[Bx * Lx];            // pre-softmax scores
__device__ float g_partial[Bx * NSPLIT * Dx]; // context partials

// offsets in d_out (float32): attn, context, new_coverage concatenated
#define ATTN_OFF 0
#define CTX_OFF  (Bx * Lx)
#define COV_OFF  (Bx * Lx + Bx * Dx)

__device__ __forceinline__ float tanh_approx(float x) {
    float y;
    asm("tanh.approx.f32 %0, %1;" : "=f"(y) : "f"(x));
    return y;
}

// ============================================================
// Kernel 1: dec_feature[b,d] = sum_k dec_hidden[b,k]*W_feat[d,k] + b_feat[d]
// grid = Dx blocks, 256 threads. Each thread owns one float4 of row d.
// ============================================================
__global__ void k_decfeat(const float* __restrict__ dh,
                          const float* __restrict__ W,
                          const float* __restrict__ bias) {
    int d = blockIdx.x;
    int t = threadIdx.x;               // 0..255
    float4 w4 = ((const float4*)(W + (size_t)d * Dx))[t];

    float acc[Bx];
#pragma unroll
    for (int b = 0; b < Bx; b++) {
        float4 h4 = ((const float4*)(dh + (size_t)b * Dx))[t];
        acc[b] = w4.x * h4.x + w4.y * h4.y + w4.z * h4.z + w4.w * h4.w;
    }
#pragma unroll
    for (int b = 0; b < Bx; b++) {
#pragma unroll
        for (int off = 16; off; off >>= 1)
            acc[b] += __shfl_down_sync(0xffffffffu, acc[b], off);
    }
    __shared__ float s[8][Bx];
    int warp = t >> 5, lane = t & 31;
    if (lane == 0) {
#pragma unroll
        for (int b = 0; b < Bx; b++) s[warp][b] = acc[b];
    }
    __syncthreads();
    if (t < Bx) {
        float v = 0.f;
#pragma unroll
        for (int w = 0; w < 8; w++) v += s[w][t];
        g_df[t * Dx + d] = v + bias[d];
    }
}

// ============================================================
// Kernel 2: score[b,l] = sum_d tanh(ef + df + cov*w_cov) * w_score
// grid = (Lx/8, Bx), 256 threads = 8 warps, one warp per l-row.
// Streams enc_feature (256 MB) — HBM bound. tanh via MUFU.TANH.
// ============================================================
__global__ void k_score(const float* __restrict__ ef,
                        const float* __restrict__ cov,
                        const float* __restrict__ wscore,
                        const float* __restrict__ wcov) {
    int b  = blockIdx.y;
    int l0 = blockIdx.x * 8;
    int t  = threadIdx.x;

    __shared__ float4 s_df[Dx / 4], s_ws[Dx / 4], s_wc[Dx / 4];
    s_df[t] = ((const float4*)(g_df + (size_t)b * Dx))[t];
    s_ws[t] = ((const float4*)wscore)[t];
    s_wc[t] = ((const float4*)wcov)[t];
    __syncthreads();

    int warp = t >> 5, lane = t & 31;
    int l = l0 + warp;
    float c = cov[b * Lx + l];
    const float4* row = (const float4*)(ef + ((size_t)b * Lx + l) * Dx);

    float sum = 0.f;
#pragma unroll
    for (int j = 0; j < 8; j++) {
        int idx = lane + j * 32;
        float4 e  = row[idx];
        float4 dv = s_df[idx];
        float4 wc = s_wc[idx];
        float4 ws = s_ws[idx];
        sum += tanh_approx(fmaf(c, wc.x, e.x + dv.x)) * ws.x
             + tanh_approx(fmaf(c, wc.y, e.y + dv.y)) * ws.y
             + tanh_approx(fmaf(c, wc.z, e.z + dv.z)) * ws.z
             + tanh_approx(fmaf(c, wc.w, e.w + dv.w)) * ws.w;
    }
#pragma unroll
    for (int off = 16; off; off >>= 1)
        sum += __shfl_down_sync(0xffffffffu, sum, off);
    if (lane == 0) g_score[b * Lx + l] = sum;
}

// ============================================================
// Kernel 3: masked softmax + renormalize, write attn & new_coverage.
// softmax -> *mask -> /sum collapses to e*m / sum(e*m).
// grid = Bx blocks, 1024 threads, 4 elems/thread.
// ============================================================
__global__ void k_softmax(const float* __restrict__ mask,
                          const float* __restrict__ cov,
                          float* __restrict__ out) {
    int b = blockIdx.x;
    int t = threadIdx.x;
    __shared__ float red[32];
    __shared__ float bcast;

    float s[4], em[4];
#pragma unroll
    for (int i = 0; i < 4; i++) s[i] = g_score[b * Lx + t + i * 1024];

    // ---- block max ----
    float mx = fmaxf(fmaxf(s[0], s[1]), fmaxf(s[2], s[3]));
#pragma unroll
    for (int off = 16; off; off >>= 1)
        mx = fmaxf(mx, __shfl_xor_sync(0xffffffffu, mx, off));
    if ((t & 31) == 0) red[t >> 5] = mx;
    __syncthreads();
    if (t < 32) {
        float v = red[t];
#pragma unroll
        for (int off = 16; off; off >>= 1)
            v = fmaxf(v, __shfl_xor_sync(0xffffffffu, v, off));
        if (t == 0) bcast = v;
    }
    __syncthreads();
    mx = bcast;

    // ---- e * mask, block sum ----
    float lsum = 0.f;
#pragma unroll
    for (int i = 0; i < 4; i++) {
        em[i] = expf(s[i] - mx) * mask[b * Lx + t + i * 1024];
        lsum += em[i];
    }
#pragma unroll
    for (int off = 16; off; off >>= 1)
        lsum += __shfl_xor_sync(0xffffffffu, lsum, off);
    __syncthreads();            // protect red[] reuse
    if ((t & 31) == 0) red[t >> 5] = lsum;
    __syncthreads();
    if (t < 32) {
        float v = red[t];
#pragma unroll
        for (int off = 16; off; off >>= 1)
            v += __shfl_xor_sync(0xffffffffu, v, off);
        if (t == 0) bcast = v;
    }
    __syncthreads();
    float inv = 1.f / bcast;

#pragma unroll
    for (int i = 0; i < 4; i++) {
        int idx = b * Lx + t + i * 1024;
        float a = em[i] * inv;
        out[ATTN_OFF + idx] = a;
        out[COV_OFF  + idx] = a + cov[idx];
    }
}

// ============================================================
// Kernel 4: context partials. grid = (NSPLIT, Bx), 256 threads.
// Thread owns one float4 of d. Streams enc_output (256 MB) — HBM bound.
// ============================================================
__global__ void k_context(const float* __restrict__ eo,
                          const float* __restrict__ attn) {
    int b  = blockIdx.y;
    int sp = blockIdx.x;     // 0..NSPLIT-1
    int t  = threadIdx.x;    // 0..255
    int l0 = sp * ROWS_PER_SPLIT;

    __shared__ float sa[ROWS_PER_SPLIT];
    if (t < ROWS_PER_SPLIT) sa[t] = attn[b * Lx + l0 + t];
    __syncthreads();

    const float4* base = (const float4*)eo + ((size_t)b * Lx + l0) * (Dx / 4) + t;
    float4 acc = make_float4(0.f, 0.f, 0.f, 0.f);
#pragma unroll 8
    for (int i = 0; i < ROWS_PER_SPLIT; i++) {
        float a = sa[i];
        float4 v = base[(size_t)i * (Dx / 4)];
        acc.x = fmaf(a, v.x, acc.x);
        acc.y = fmaf(a, v.y, acc.y);
        acc.z = fmaf(a, v.z, acc.z);
        acc.w = fmaf(a, v.w, acc.w);
    }
    ((float4*)(g_partial + ((size_t)(b * NSPLIT + sp)) * Dx))[t] = acc;
}

// ============================================================
// Kernel 5: deterministic partial reduce -> context. 16384 outputs.
// ============================================================
__global__ void k_reduce(float* __restrict__ out) {
    int idx = blockIdx.x * 256 + threadIdx.x;   // 0..16383
    int b = idx >> 10, d = idx & 1023;
    float v = 0.f;
#pragma unroll
    for (int s = 0; s < NSPLIT; s++)
        v += g_partial[((size_t)(b * NSPLIT + s) << 10) + d];
    out[CTX_OFF + idx] = v;
}

// ============================================================
extern "C" void kernel_launch(void* const* d_in, const int* in_sizes, int n_in,
                              void* d_out, int out_size) {
    const float* dec_hidden  = (const float*)d_in[0];
    const float* enc_output  = (const float*)d_in[1];
    const float* enc_feature = (const float*)d_in[2];
    const float* enc_mask    = (const float*)d_in[3];
    // d_in[4] = sec_attn : dead code in reference
    const float* coverage    = (const float*)d_in[5];
    const float* W_feat      = (const float*)d_in[6];
    const float* b_feat      = (const float*)d_in[7];
    const float* w_score     = (const float*)d_in[8];
    const float* w_cov       = (const float*)d_in[9];
    float* out = (float*)d_out;

    k_decfeat<<<Dx, 256>>>(dec_hidden, W_feat, b_feat);
    k_score  <<<dim3(Lx / 8, Bx), 256>>>(enc_feature, coverage, w_score, w_cov);
    k_softmax<<<Bx, 1024>>>(enc_mask, coverage, out);
    k_context<<<dim3(NSPLIT, Bx), 256>>>(enc_output, out + ATTN_OFF);
    k_reduce <<<(Bx * Dx) / 256, 256>>>(out);
}